// round 1
// baseline (speedup 1.0000x reference)
#include <cuda_runtime.h>

// VanillaGaussianFieldHead: masked gather + SH basis (deg<=3) + per-channel dot.
// Inputs (metadata order):
//  0: means        (N,3)  f32
//  1: features_dc  (N,3)  f32
//  2: features_rest(N,45) f32
//  3: opacities    (N,1)  f32
//  4: camera_to_worlds (3,4) f32
//  5: mask_idx     (M,)   i32
//  6: step         ()     i32
// Output: rgbs (M,3) f32 followed by opac (M,1) f32, concatenated flat.

#define TILE 128
#define STRIDE 53  // 52 payload floats + 1 pad (odd stride => conflict-free LDS)

__global__ __launch_bounds__(TILE)
void vgfh_kernel(const float* __restrict__ means,
                 const float* __restrict__ dc,
                 const float* __restrict__ rest,
                 const float* __restrict__ opac,
                 const float* __restrict__ cam,
                 const int*   __restrict__ mask_idx,
                 const int*   __restrict__ step_p,
                 float* __restrict__ out,
                 int M)
{
    __shared__ float s[TILE * STRIDE];

    const int tid  = threadIdx.x;
    const int lane = tid & 31;
    const int w    = tid >> 5;
    const int blockBase = blockIdx.x * TILE;
    const int e0 = blockBase + w * 32;   // this warp stages elements [e0, e0+32)

    // Preload this warp's 32 indices (coalesced).
    int idxv = 0;
    {
        int eLane = e0 + lane;
        if (eLane < M) idxv = __ldg(&mask_idx[eLane]);
    }

    const int cnt = min(32, M - e0);  // uniform across warp
    for (int i = 0; i < cnt; i++) {
        const int idx    = __shfl_sync(0xffffffffu, idxv, i);
        const int base45 = idx * 45;
        const int sBase  = (w * 32 + i) * STRIDE;

        // LDG #1: rest[0..31] of the row — contiguous, coalesced.
        s[sBase + lane] = __ldg(&rest[base45 + lane]);

        // LDG #2: mixed tail — rest[32..44], dc[0..2], means[0..2], opac.
        if (lane < 20) {
            const float* p;
            if (lane < 13)      p = &rest[base45 + 32 + lane];     // slots 32..44
            else if (lane < 16) p = &dc[idx * 3 + (lane - 13)];    // slots 45..47
            else if (lane < 19) p = &means[idx * 3 + (lane - 16)]; // slots 48..50
            else                p = &opac[idx];                    // slot  51
            s[sBase + 32 + lane] = __ldg(p);
        }
    }
    __syncthreads();

    const int e = blockBase + tid;
    if (e >= M) return;

    const float* f = &s[tid * STRIDE];

    // Camera position = column 3 of (3,4) row-major matrix.
    const float cx = __ldg(&cam[3]);
    const float cy = __ldg(&cam[7]);
    const float cz = __ldg(&cam[11]);

    const float dxv = f[48] - cx;
    const float dyv = f[49] - cy;
    const float dzv = f[50] - cz;
    const float rn  = rsqrtf(dxv * dxv + dyv * dyv + dzv * dzv);
    const float x = dxv * rn, y = dyv * rn, z = dzv * rn;

    const int deg = min(__ldg(step_p) / 1000, 3);

    // Base 0 (dc) in slots 45..47.
    const float C0 = 0.28209479177387814f;
    float rr = C0 * f[45];
    float gg = C0 * f[46];
    float bb = C0 * f[47];

    const float xx = x * x, yy = y * y, zz = z * z;
    const float xy = x * y, yz = y * z, xz = x * z;

    if (deg >= 1) {
        const float C1 = 0.4886025119029199f;
        const float b1 = -C1 * y, b2 = C1 * z, b3 = -C1 * x;
        rr += b1 * f[0] + b2 * f[3] + b3 * f[6];
        gg += b1 * f[1] + b2 * f[4] + b3 * f[7];
        bb += b1 * f[2] + b2 * f[5] + b3 * f[8];
    }
    if (deg >= 2) {
        const float b4 =  1.0925484305920792f * xy;
        const float b5 = -1.0925484305920792f * yz;
        const float b6 =  0.31539156525252005f * (2.0f * zz - xx - yy);
        const float b7 = -1.0925484305920792f * xz;
        const float b8 =  0.5462742152960396f * (xx - yy);
        rr += b4 * f[9]  + b5 * f[12] + b6 * f[15] + b7 * f[18] + b8 * f[21];
        gg += b4 * f[10] + b5 * f[13] + b6 * f[16] + b7 * f[19] + b8 * f[22];
        bb += b4 * f[11] + b5 * f[14] + b6 * f[17] + b7 * f[20] + b8 * f[23];
    }
    if (deg >= 3) {
        const float b9  = -0.5900435899266435f * y * (3.0f * xx - yy);
        const float b10 =  2.890611442640554f  * xy * z;
        const float b11 = -0.4570457994644658f * y * (4.0f * zz - xx - yy);
        const float b12 =  0.3731763325901154f * z * (2.0f * zz - 3.0f * xx - 3.0f * yy);
        const float b13 = -0.4570457994644658f * x * (4.0f * zz - xx - yy);
        const float b14 =  1.445305721320277f  * z * (xx - yy);
        const float b15 = -0.5900435899266435f * x * (xx - 3.0f * yy);
        rr += b9 * f[24] + b10 * f[27] + b11 * f[30] + b12 * f[33]
            + b13 * f[36] + b14 * f[39] + b15 * f[42];
        gg += b9 * f[25] + b10 * f[28] + b11 * f[31] + b12 * f[34]
            + b13 * f[37] + b14 * f[40] + b15 * f[43];
        bb += b9 * f[26] + b10 * f[29] + b11 * f[32] + b12 * f[35]
            + b13 * f[38] + b14 * f[41] + b15 * f[44];
    }

    rr = fmaxf(rr + 0.5f, 0.0f);
    gg = fmaxf(gg + 0.5f, 0.0f);
    bb = fmaxf(bb + 0.5f, 0.0f);

    out[e * 3 + 0] = rr;
    out[e * 3 + 1] = gg;
    out[e * 3 + 2] = bb;
    out[(size_t)3 * M + e] = f[51];  // opacity passthrough
}

extern "C" void kernel_launch(void* const* d_in, const int* in_sizes, int n_in,
                              void* d_out, int out_size) {
    const float* means = (const float*)d_in[0];
    const float* dc    = (const float*)d_in[1];
    const float* rest  = (const float*)d_in[2];
    const float* opac  = (const float*)d_in[3];
    const float* cam   = (const float*)d_in[4];
    const int*   midx  = (const int*)d_in[5];
    const int*   step  = (const int*)d_in[6];
    float* out = (float*)d_out;

    const int M = in_sizes[5];
    const int grid = (M + TILE - 1) / TILE;
    vgfh_kernel<<<grid, TILE>>>(means, dc, rest, opac, cam, midx, step, out, M);
}

// round 3
// speedup vs baseline: 1.9268x; 1.9268x over previous
#include <cuda_runtime.h>
#include <cstdint>

// VanillaGaussianFieldHead: masked gather + SH basis (deg<=3) + per-channel dot.
// Inputs (metadata order):
//  0: means (N,3) f32   1: features_dc (N,3) f32   2: features_rest (N,45) f32
//  3: opacities (N,1) f32   4: camera_to_worlds (3,4) f32
//  5: mask_idx (M,) i32     6: step () i32
// Output: rgbs (M,3) f32 followed by opac (M,1) f32, flat.

#define TILE 128
// 52 payload floats per element: [0..44]=rest, [45..47]=dc, [48..50]=means, [51]=opac.
// Stride 52 floats = 208 B: 16B-aligned rows AND conflict-free for LDS.128
// (lane l phase banks: 20*l mod 32 covers all 32 banks disjointly).
#define STRIDE 52

__device__ __forceinline__ void cp_async4(unsigned int saddr, const void* gptr) {
    asm volatile("cp.async.ca.shared.global [%0], [%1], 4;\n"
                 :: "r"(saddr), "l"(gptr) : "memory");
}

__global__ void __launch_bounds__(TILE)
vgfh_kernel(const float* __restrict__ means,
            const float* __restrict__ dc,
            const float* __restrict__ rest,
            const float* __restrict__ opac,
            const float* __restrict__ cam,
            const int*   __restrict__ mask_idx,
            const int*   __restrict__ step_p,
            float* __restrict__ out,
            int M)
{
    __shared__ __align__(16) float s[TILE * STRIDE];

    const int tid  = threadIdx.x;
    const int lane = tid & 31;
    const int w    = tid >> 5;
    const int e0   = blockIdx.x * TILE + w * 32;  // warp's 32 elements

    // Coalesced index load; each lane keeps its own element's index.
    int idxv = 0;
    if (e0 + lane < M) idxv = __ldg(&mask_idx[e0 + lane]);

    // Per-lane source formula for the mixed tail cp.async (computed ONCE):
    //   lanes 0..12  -> rest[idx*45 + 32 + lane]   (slots 32..44)
    //   lanes 13..15 -> dc[idx*3 + lane-13]        (slots 45..47)
    //   lanes 16..18 -> means[idx*3 + lane-16]     (slots 48..50)
    //   lane  19     -> opac[idx]                  (slot  51)
    const float* base2 = opac;
    int scale2 = 1;
    if (lane < 13)      { base2 = rest  + 32 + lane;   scale2 = 45; }
    else if (lane < 16) { base2 = dc    + (lane - 13); scale2 = 3;  }
    else if (lane < 19) { base2 = means + (lane - 16); scale2 = 3;  }

    const unsigned int srow = (unsigned int)__cvta_generic_to_shared(&s[(w * 32) * STRIDE]);
    const unsigned int sl1  = srow + (unsigned int)(lane * 4);         // slot lane
    const unsigned int sl2  = srow + (unsigned int)((32 + lane) * 4);  // slot 32+lane

    const int cnt = min(32, M - e0);
    for (int i = 0; i < cnt; i++) {
        const int idx = __shfl_sync(0xffffffffu, idxv, i);
        const unsigned int soff = (unsigned int)(i * (STRIDE * 4));
        // rest[0..31] of the row: contiguous 128B, fire-and-forget.
        cp_async4(sl1 + soff, rest + idx * 45 + lane);
        // mixed tail: rest[32..44] | dc | means | opac.
        if (lane < 20) {
            cp_async4(sl2 + soff, base2 + idx * scale2);
        }
    }
    asm volatile("cp.async.commit_group;\n" ::: "memory");
    asm volatile("cp.async.wait_group 0;\n" ::: "memory");
    __syncwarp();

    const int e = blockIdx.x * TILE + tid;
    if (e >= M) return;

    // 13 conflict-free LDS.128 -> everything in registers.
    float f[STRIDE];
    {
        const float4* sp = reinterpret_cast<const float4*>(&s[tid * STRIDE]);
        #pragma unroll
        for (int i = 0; i < 13; i++) {
            float4 v = sp[i];
            f[4 * i + 0] = v.x; f[4 * i + 1] = v.y;
            f[4 * i + 2] = v.z; f[4 * i + 3] = v.w;
        }
    }

    // Camera position = column 3 of (3,4) row-major matrix (L1-resident).
    const float cx = __ldg(&cam[3]);
    const float cy = __ldg(&cam[7]);
    const float cz = __ldg(&cam[11]);

    const float dxv = f[48] - cx;
    const float dyv = f[49] - cy;
    const float dzv = f[50] - cz;
    const float rn  = rsqrtf(dxv * dxv + dyv * dyv + dzv * dzv);
    const float x = dxv * rn, y = dyv * rn, z = dzv * rn;

    const int deg = min(__ldg(step_p) / 1000, 3);

    const float C0 = 0.28209479177387814f;
    float rr = C0 * f[45];
    float gg = C0 * f[46];
    float bb = C0 * f[47];

    const float xx = x * x, yy = y * y, zz = z * z;
    const float xy = x * y, yz = y * z, xz = x * z;

    if (deg >= 1) {
        const float C1 = 0.4886025119029199f;
        const float b1 = -C1 * y, b2 = C1 * z, b3 = -C1 * x;
        rr += b1 * f[0] + b2 * f[3] + b3 * f[6];
        gg += b1 * f[1] + b2 * f[4] + b3 * f[7];
        bb += b1 * f[2] + b2 * f[5] + b3 * f[8];
    }
    if (deg >= 2) {
        const float b4 =  1.0925484305920792f * xy;
        const float b5 = -1.0925484305920792f * yz;
        const float b6 =  0.31539156525252005f * (2.0f * zz - xx - yy);
        const float b7 = -1.0925484305920792f * xz;
        const float b8 =  0.5462742152960396f * (xx - yy);
        rr += b4 * f[9]  + b5 * f[12] + b6 * f[15] + b7 * f[18] + b8 * f[21];
        gg += b4 * f[10] + b5 * f[13] + b6 * f[16] + b7 * f[19] + b8 * f[22];
        bb += b4 * f[11] + b5 * f[14] + b6 * f[17] + b7 * f[20] + b8 * f[23];
    }
    if (deg >= 3) {
        const float b9  = -0.5900435899266435f * y * (3.0f * xx - yy);
        const float b10 =  2.890611442640554f  * xy * z;
        const float b11 = -0.4570457994644658f * y * (4.0f * zz - xx - yy);
        const float b12 =  0.3731763325901154f * z * (2.0f * zz - 3.0f * xx - 3.0f * yy);
        const float b13 = -0.4570457994644658f * x * (4.0f * zz - xx - yy);
        const float b14 =  1.445305721320277f  * z * (xx - yy);
        const float b15 = -0.5900435899266435f * x * (xx - 3.0f * yy);
        rr += b9 * f[24] + b10 * f[27] + b11 * f[30] + b12 * f[33]
            + b13 * f[36] + b14 * f[39] + b15 * f[42];
        gg += b9 * f[25] + b10 * f[28] + b11 * f[31] + b12 * f[34]
            + b13 * f[37] + b14 * f[40] + b15 * f[43];
        bb += b9 * f[26] + b10 * f[29] + b11 * f[32] + b12 * f[35]
            + b13 * f[38] + b14 * f[41] + b15 * f[44];
    }

    rr = fmaxf(rr + 0.5f, 0.0f);
    gg = fmaxf(gg + 0.5f, 0.0f);
    bb = fmaxf(bb + 0.5f, 0.0f);

    out[e * 3 + 0] = rr;
    out[e * 3 + 1] = gg;
    out[e * 3 + 2] = bb;
    out[(size_t)3 * M + e] = f[51];  // opacity passthrough
}

extern "C" void kernel_launch(void* const* d_in, const int* in_sizes, int n_in,
                              void* d_out, int out_size) {
    const float* means = (const float*)d_in[0];
    const float* dc    = (const float*)d_in[1];
    const float* rest  = (const float*)d_in[2];
    const float* opac  = (const float*)d_in[3];
    const float* cam   = (const float*)d_in[4];
    const int*   midx  = (const int*)d_in[5];
    const int*   step  = (const int*)d_in[6];
    float* out = (float*)d_out;

    const int M = in_sizes[5];
    const int grid = (M + TILE - 1) / TILE;
    vgfh_kernel<<<grid, TILE>>>(means, dc, rest, opac, cam, midx, step, out, M);
}